// round 1
// baseline (speedup 1.0000x reference)
#include <cuda_runtime.h>
#include <cstddef>

#define NN 64          // sequence length
#define TB 128         // threads per block = batches per block

// robust NaN->0 (bit test, immune to fast-math folding)
__device__ __forceinline__ float nan0(float h) {
    unsigned u = __float_as_uint(h);
    return ((u & 0x7fffffffu) > 0x7f800000u) ? 0.0f : h;
}

__global__ __launch_bounds__(TB, 2)
void tdvp_kernel(const float* __restrict__ xg, const float* __restrict__ Ag,
                 const float* __restrict__ Bg, const float* __restrict__ sg,
                 float* __restrict__ yg)
{
    extern __shared__ char smem_raw[];
    float*  sA = (float*)smem_raw;              // [NN*32]  A[n,l,r,i]
    float*  sB = sA + NN * 32;                  // [NN*64]  B[n,i,l,j,k]
    float2* sx = (float2*)(sB + NN * 64);       // [TB*(NN+1)] xn (then reused for y)

    const int tid = threadIdx.x;
    const int b0  = blockIdx.x * TB;

    for (int i = tid; i < NN * 32; i += TB) sA[i] = Ag[i];
    for (int i = tid; i < NN * 64; i += TB) sB[i] = Bg[i];

    // stage x (coalesced) and normalize each (b,n) 2-vector
    const float2* xv = (const float2*)xg;
    for (int idx = tid; idx < TB * NN; idx += TB) {
        float2 v = xv[(size_t)b0 * NN + idx];
        float inv = rsqrtf(v.x * v.x + v.y * v.y);
        v.x *= inv; v.y *= inv;
        sx[(idx >> 6) * (NN + 1) + (idx & 63)] = v;
    }
    __syncthreads();

    float2* myx = &sx[tid * (NN + 1)];

    float m[16];
    auto loadM = [&](int n) {
        float2 xn = myx[n];
        const float* a = &sA[n * 32];
        #pragma unroll
        for (int e = 0; e < 16; ++e)
            m[e] = fmaf(a[2 * e], xn.x, a[2 * e + 1] * xn.y);
    };

    // ---------------- backward pass: suffix products ----------------
    // arl[n] = normalize( M[n+1] * ... * M[63] * e0 ),  n = 0..62
    float4 arl[NN - 1];
    {
        loadM(NN - 1);
        float r0 = m[0], r1 = m[4], r2 = m[8], r3 = m[12];   // column 0 of M[63]
        #pragma unroll 1
        for (int n = NN - 2; n >= 0; --n) {
            float nrm = sqrtf(r0*r0 + r1*r1 + r2*r2 + r3*r3);
            float inv = 1.0f / (nrm + 1e-6f);
            arl[n] = make_float4(r0 * inv, r1 * inv, r2 * inv, r3 * inv);
            if (n > 0) {
                loadM(n);
                float t0 = m[0]*r0  + m[1]*r1  + m[2]*r2  + m[3]*r3;
                float t1 = m[4]*r0  + m[5]*r1  + m[6]*r2  + m[7]*r3;
                float t2 = m[8]*r0  + m[9]*r1  + m[10]*r2 + m[11]*r3;
                float t3 = m[12]*r0 + m[13]*r1 + m[14]*r2 + m[15]*r3;
                r0 = t0; r1 = t1; r2 = t2; r3 = t3;
            }
        }
    }

    // ---------------- forward pass + output ----------------
    const float s = sg[0];
    float v0 = 0.f, v1 = 0.f, v2 = 0.f, v3 = 0.f;   // raw prefix e0^T M[0..n-1]
    #pragma unroll 1
    for (int n = 0; n < NN; ++n) {
        loadM(n);

        float u0, u1, u2, u3;
        if (n == 0) { u0 = 1.f; u1 = 0.f; u2 = 0.f; u3 = 0.f; }
        else {
            float nrm = sqrtf(v0*v0 + v1*v1 + v2*v2 + v3*v3);
            float inv = 1.0f / (nrm + 1e-6f);
            u0 = v0 * inv; u1 = v1 * inv; u2 = v2 * inv; u3 = v3 * inv;
        }

        float a0, a1, a2, a3;
        if (n == NN - 1) { a0 = 1.f; a1 = 0.f; a2 = 0.f; a3 = 0.f; }
        else { float4 t = arl[n]; a0 = t.x; a1 = t.y; a2 = t.z; a3 = t.w; }

        float uu[4] = {u0, u1, u2, u3};
        float aa[4] = {a0, a1, a2, a3};

        float H00 = 0.f, H01 = 0.f, H10 = 0.f, H11 = 0.f;
        const float* bb = &sB[n * 64];
        #pragma unroll
        for (int i = 0; i < 4; ++i) {
            #pragma unroll
            for (int l = 0; l < 4; ++l) {
                float w = uu[i] * aa[l];
                const float* p = bb + i * 16 + l * 4;
                H00 = fmaf(w, p[0], H00);
                H01 = fmaf(w, p[1], H01);
                H10 = fmaf(w, p[2], H10);
                H11 = fmaf(w, p[3], H11);
            }
        }

        float f    = sqrtf(H00*H00 + H01*H01 + H10*H10 + H11*H11);
        float invf = s / (f + 1e-6f);
        H00 = fmaxf(nan0(H00 * invf), 0.f);
        H01 = fmaxf(nan0(H01 * invf), 0.f);
        H10 = fmaxf(nan0(H10 * invf), 0.f);
        H11 = fmaxf(nan0(H11 * invf), 0.f);

        float2 xn = myx[n];
        float y0 = fmaf(H00, xn.x, H01 * xn.y);
        float y1 = fmaf(H10, xn.x, H11 * xn.y);
        myx[n] = make_float2(y0, y1);   // stash y for coalesced writeback

        // prefix update: v <- v * M[n]  (row-vector times matrix)
        if (n == 0) { v0 = m[0]; v1 = m[1]; v2 = m[2]; v3 = m[3]; }
        else {
            float t0 = v0*m[0] + v1*m[4] + v2*m[8]  + v3*m[12];
            float t1 = v0*m[1] + v1*m[5] + v2*m[9]  + v3*m[13];
            float t2 = v0*m[2] + v1*m[6] + v2*m[10] + v3*m[14];
            float t3 = v0*m[3] + v1*m[7] + v2*m[11] + v3*m[15];
            v0 = t0; v1 = t1; v2 = t2; v3 = t3;
        }
    }
    __syncthreads();

    // coalesced writeback of y
    float2* yv = (float2*)yg;
    for (int idx = tid; idx < TB * NN; idx += TB)
        yv[(size_t)b0 * NN + idx] = sx[(idx >> 6) * (NN + 1) + (idx & 63)];
}

extern "C" void kernel_launch(void* const* d_in, const int* in_sizes, int n_in,
                              void* d_out, int out_size) {
    const float* x = (const float*)d_in[0];
    const float* A = (const float*)d_in[1];
    const float* B = (const float*)d_in[2];
    const float* s = (const float*)d_in[3];
    float* y = (float*)d_out;

    const int batch = in_sizes[0] / (NN * 2);
    const int grid  = batch / TB;

    const size_t smem = (size_t)(NN * 32 + NN * 64) * sizeof(float)
                      + (size_t)TB * (NN + 1) * sizeof(float2);

    cudaFuncSetAttribute(tdvp_kernel, cudaFuncAttributeMaxDynamicSharedMemorySize, (int)smem);
    tdvp_kernel<<<grid, TB, smem>>>(x, A, B, s, y);
}

// round 2
// speedup vs baseline: 1.0048x; 1.0048x over previous
#include <cuda_runtime.h>
#include <cstddef>

#define NN 64          // sequence length
#define TB 128         // threads per block
#define G  16          // batches per block (8 threads per batch)

// robust NaN->0 (bit test, immune to fast-math folding)
__device__ __forceinline__ float nan0(float h) {
    unsigned u = __float_as_uint(h);
    return ((u & 0x7fffffffu) > 0x7f800000u) ? 0.0f : h;
}

__device__ __forceinline__ float sh4(float v, int src) {
    return __shfl_sync(0xffffffffu, v, src, 4);
}

// shared layout (floats):
//  sA  [NN*32]            A[n,l,r,i]  (row-major rows: for backward)
//  sAT [NN*32]            A^T per n: [n, r, l, i] (for forward columns)
//  sB  [NN*68]            B[n,...] padded stride 68 (bank spread)
//  sx  [G*65] float2      normalized x (then y), padded row stride 65
//  svL [G*65] float4      raw prefix vectors, padded row stride 65
//  svR [G*65] float4      raw suffix vectors
#define SA_OFF   0
#define SAT_OFF  (NN*32)
#define SB_OFF   (NN*64)
#define SB_STR   68
#define SX_OFF   (SB_OFF + NN*SB_STR)          // in floats; float2 array
#define SVL_OFF  (SX_OFF + G*65*2)             // float4 array
#define SVR_OFF  (SVL_OFF + G*65*4)
#define SMEM_FLOATS (SVR_OFF + G*65*4)

__global__ __launch_bounds__(TB, 3)
void tdvp_kernel(const float* __restrict__ xg, const float* __restrict__ Ag,
                 const float* __restrict__ Bg, const float* __restrict__ sg,
                 float* __restrict__ yg)
{
    extern __shared__ float sm[];
    float*  sA  = sm + SA_OFF;
    float*  sAT = sm + SAT_OFF;
    float*  sB  = sm + SB_OFF;
    float2* sx  = (float2*)(sm + SX_OFF);
    float4* svL = (float4*)(sm + SVL_OFF);
    float4* svR = (float4*)(sm + SVR_OFF);

    const int tid = threadIdx.x;
    const int b0  = blockIdx.x * G;

    // ---- stage A (and transposed copy), B, x ----
    for (int i = tid; i < NN * 32; i += TB) {
        float a = Ag[i];
        sA[i] = a;
        int n = i >> 5, rem = i & 31;
        int l = rem >> 3, r = (rem >> 1) & 3, ii = i & 1;
        sAT[n * 32 + (r * 4 + l) * 2 + ii] = a;       // [n][r][l][i]
    }
    for (int i = tid; i < NN * 64; i += TB) {
        int n = i >> 6;
        sB[n * SB_STR + (i & 63)] = Bg[i];
    }
    const float2* xv = (const float2*)xg;
    for (int idx = tid; idx < G * NN; idx += TB) {
        float2 v = xv[(size_t)b0 * NN + idx];
        float inv = rsqrtf(v.x * v.x + v.y * v.y);
        v.x *= inv; v.y *= inv;
        sx[(idx >> 6) * 65 + (idx & 63)] = v;
    }
    __syncthreads();

    // ---- chain phase: warps 0-1 forward, warps 2-3 backward ----
    {
        const int role = tid >> 6;        // 0 = forward, 1 = backward
        const int rem  = tid & 63;
        const int g    = rem >> 2;        // batch in block
        const int ln   = rem & 3;         // component owned by this lane
        const float2* gx = sx + g * 65;

        if (role == 0) {
            // forward: v = e0^T M[0..n-1]; lane ln holds v_ln.
            // svL[n] = raw prefix used at position n (n = 1..63)
            float* Lp = (float*)(svL + g * 65);
            float2 x0 = gx[0];
            // v_k = M[0][0][k] = A[0, l=0, r=k, :] . x0  -> sAT[0*32 + k*8 + 0*2 + i]
            float v = fmaf(sAT[ln * 8], x0.x, sAT[ln * 8 + 1] * x0.y);
            Lp[1 * 4 + ln] = v;
            #pragma unroll 4
            for (int n = 1; n < NN - 1; ++n) {
                float2 xn = gx[n];
                const float4* ct = (const float4*)(sAT + n * 32 + ln * 8);
                float4 a0 = ct[0], a1 = ct[1];
                // column ln of M[n]: entries j = 0..3
                float m0 = fmaf(a0.x, xn.x, a0.y * xn.y);
                float m1 = fmaf(a0.z, xn.x, a0.w * xn.y);
                float m2 = fmaf(a1.x, xn.x, a1.y * xn.y);
                float m3 = fmaf(a1.z, xn.x, a1.w * xn.y);
                float nv = sh4(v, 0) * m0;
                nv = fmaf(sh4(v, 1), m1, nv);
                nv = fmaf(sh4(v, 2), m2, nv);
                nv = fmaf(sh4(v, 3), m3, nv);
                v = nv;
                Lp[(n + 1) * 4 + ln] = v;
            }
        } else {
            // backward: r = M[n+1..63] e0; lane ln holds r_ln.
            // svR[n] = raw suffix used at position n (n = 0..62)
            float* Rp = (float*)(svR + g * 65);
            float2 x63 = gx[NN - 1];
            // r_j = M[63][j][0] = A[63, l=j, r=0, :] . x63
            const float* rw0 = sA + (NN - 1) * 32 + ln * 8;
            float r = fmaf(rw0[0], x63.x, rw0[1] * x63.y);
            Rp[(NN - 2) * 4 + ln] = r;
            #pragma unroll 4
            for (int n = NN - 2; n >= 1; --n) {
                float2 xn = gx[n];
                const float4* rw = (const float4*)(sA + n * 32 + ln * 8);
                float4 a0 = rw[0], a1 = rw[1];
                // row ln of M[n]: entries k = 0..3
                float m0 = fmaf(a0.x, xn.x, a0.y * xn.y);
                float m1 = fmaf(a0.z, xn.x, a0.w * xn.y);
                float m2 = fmaf(a1.x, xn.x, a1.y * xn.y);
                float m3 = fmaf(a1.z, xn.x, a1.w * xn.y);
                float nr = m0 * sh4(r, 0);
                nr = fmaf(m1, sh4(r, 1), nr);
                nr = fmaf(m2, sh4(r, 2), nr);
                nr = fmaf(m3, sh4(r, 3), nr);
                r = nr;
                Rp[(n - 1) * 4 + ln] = r;
            }
        }
    }
    __syncthreads();

    // ---- output phase: 8 threads per batch, 8 n-values each ----
    {
        const int g   = tid >> 3;         // 0..15
        const int sub = tid & 7;
        float2* gx = sx + g * 65;
        const float4* L = svL + g * 65;
        const float4* R = svR + g * 65;
        const float s = sg[0];

        #pragma unroll 2
        for (int t = 0; t < 8; ++t) {
            int n = sub + 8 * t;

            float u0, u1, u2, u3;
            if (n == 0) { u0 = 1.f; u1 = 0.f; u2 = 0.f; u3 = 0.f; }
            else {
                float4 vl = L[n];
                float nrm = sqrtf(vl.x*vl.x + vl.y*vl.y + vl.z*vl.z + vl.w*vl.w);
                float inv = 1.0f / (nrm + 1e-6f);
                u0 = vl.x * inv; u1 = vl.y * inv; u2 = vl.z * inv; u3 = vl.w * inv;
            }
            float a0, a1, a2, a3;
            if (n == NN - 1) { a0 = 1.f; a1 = 0.f; a2 = 0.f; a3 = 0.f; }
            else {
                float4 vr = R[n];
                float nrm = sqrtf(vr.x*vr.x + vr.y*vr.y + vr.z*vr.z + vr.w*vr.w);
                float inv = 1.0f / (nrm + 1e-6f);
                a0 = vr.x * inv; a1 = vr.y * inv; a2 = vr.z * inv; a3 = vr.w * inv;
            }

            float uu[4] = {u0, u1, u2, u3};
            float aa[4] = {a0, a1, a2, a3};
            float H00 = 0.f, H01 = 0.f, H10 = 0.f, H11 = 0.f;
            const float* bb = sB + n * SB_STR;
            #pragma unroll
            for (int i = 0; i < 4; ++i) {
                #pragma unroll
                for (int l = 0; l < 4; ++l) {
                    float w = uu[i] * aa[l];
                    float4 bv = *(const float4*)(bb + i * 16 + l * 4);
                    H00 = fmaf(w, bv.x, H00);
                    H01 = fmaf(w, bv.y, H01);
                    H10 = fmaf(w, bv.z, H10);
                    H11 = fmaf(w, bv.w, H11);
                }
            }

            float f    = sqrtf(H00*H00 + H01*H01 + H10*H10 + H11*H11);
            float invf = s / (f + 1e-6f);
            H00 = fmaxf(nan0(H00 * invf), 0.f);
            H01 = fmaxf(nan0(H01 * invf), 0.f);
            H10 = fmaxf(nan0(H10 * invf), 0.f);
            H11 = fmaxf(nan0(H11 * invf), 0.f);

            float2 xn = gx[n];
            float y0 = fmaf(H00, xn.x, H01 * xn.y);
            float y1 = fmaf(H10, xn.x, H11 * xn.y);
            gx[n] = make_float2(y0, y1);   // stash y for coalesced writeback
        }
    }
    __syncthreads();

    // ---- coalesced writeback ----
    float2* yv = (float2*)yg;
    for (int idx = tid; idx < G * NN; idx += TB)
        yv[(size_t)b0 * NN + idx] = sx[(idx >> 6) * 65 + (idx & 63)];
}

extern "C" void kernel_launch(void* const* d_in, const int* in_sizes, int n_in,
                              void* d_out, int out_size) {
    const float* x = (const float*)d_in[0];
    const float* A = (const float*)d_in[1];
    const float* B = (const float*)d_in[2];
    const float* s = (const float*)d_in[3];
    float* y = (float*)d_out;

    const int batch = in_sizes[0] / (NN * 2);
    const int grid  = batch / G;
    const size_t smem = (size_t)SMEM_FLOATS * sizeof(float);

    cudaFuncSetAttribute(tdvp_kernel, cudaFuncAttributeMaxDynamicSharedMemorySize, (int)smem);
    tdvp_kernel<<<grid, TB, smem>>>(x, A, B, s, y);
}